// round 8
// baseline (speedup 1.0000x reference)
#include <cuda_runtime.h>
#include <cstdint>

// ScalarRoPEEmbedding:
//   positions:      int32 [8, 8192]
//   sin_cos_cache:  fp32  [10000, 256, 2]   row = 512 floats = 128 float4
//   out:            fp32  [8, 8192, 512]
// out row = cache row with each (sin,cos) float pair swapped.
//
// R7: persistent grid-stride kernel. Exactly 5 CTAs/SM resident (40 warps/SM,
// ~40-46 regs/thread fits the RF) for the whole kernel: one wave, no
// wave-transition stalls or tail quantization. Each warp iterates over row
// PAIRS: 8 front-batched __ldg float4 gathers (MLP=8) + 8 st.global.cs
// streaming stores (output must not evict the 20MB table from L2).
// Kernel is LTS-bound: 268MB through L2 @ ~12 TB/s cap -> ~22us floor.

static constexpr int ROW_VEC4 = 128;     // float4 per 512-dim row
static constexpr int N_ROWS   = 8 * 8192;
static constexpr int N_PAIRS  = N_ROWS / 2;          // 32768 row pairs
static constexpr int THREADS  = 256;
static constexpr int WARPS_PER_BLOCK = THREADS / 32;
static constexpr int SM_COUNT = 148;
static constexpr int CTAS_PER_SM = 5;                // 40 warps/SM resident
static constexpr int GRID = SM_COUNT * CTAS_PER_SM;  // 740
static constexpr int TOTAL_WARPS = GRID * WARPS_PER_BLOCK; // 5920

__device__ __forceinline__ void stcs(float4* p, float4 v) {
    asm volatile("st.global.cs.v4.f32 [%0], {%1,%2,%3,%4};"
                 :: "l"(p), "f"(v.x), "f"(v.y), "f"(v.z), "f"(v.w) : "memory");
}

__device__ __forceinline__ float4 swap_pairs(float4 v) {
    float4 o;
    o.x = v.y; o.y = v.x; o.z = v.w; o.w = v.z;
    return o;
}

__global__ void __launch_bounds__(THREADS)
rope_gather_kernel(const int* __restrict__ positions,
                   const float4* __restrict__ cache,
                   float4* __restrict__ out)
{
    const int warp_global = blockIdx.x * WARPS_PER_BLOCK + (threadIdx.x >> 5);
    const int lane        = threadIdx.x & 31;

    for (int pair = warp_global; pair < N_PAIRS; pair += TOTAL_WARPS) {
        const int row0 = pair * 2;
        const int row1 = row0 + 1;

        const int pos0 = __ldg(positions + row0);   // warp-uniform broadcast
        const int pos1 = __ldg(positions + row1);

        const float4* __restrict__ src0 = cache + pos0 * ROW_VEC4 + lane;
        const float4* __restrict__ src1 = cache + pos1 * ROW_VEC4 + lane;
        float4* __restrict__ dst0 = out + row0 * ROW_VEC4 + lane;
        float4* __restrict__ dst1 = out + row1 * ROW_VEC4 + lane;

        // Front-batch 8 independent gathers (MLP=8)
        float4 a0 = __ldg(src0);
        float4 a1 = __ldg(src0 + 32);
        float4 a2 = __ldg(src0 + 64);
        float4 a3 = __ldg(src0 + 96);
        float4 b0 = __ldg(src1);
        float4 b1 = __ldg(src1 + 32);
        float4 b2 = __ldg(src1 + 64);
        float4 b3 = __ldg(src1 + 96);

        stcs(dst0,      swap_pairs(a0));
        stcs(dst0 + 32, swap_pairs(a1));
        stcs(dst0 + 64, swap_pairs(a2));
        stcs(dst0 + 96, swap_pairs(a3));
        stcs(dst1,      swap_pairs(b0));
        stcs(dst1 + 32, swap_pairs(b1));
        stcs(dst1 + 64, swap_pairs(b2));
        stcs(dst1 + 96, swap_pairs(b3));
    }
}

extern "C" void kernel_launch(void* const* d_in, const int* in_sizes, int n_in,
                              void* d_out, int out_size)
{
    const int*    positions = (const int*)d_in[0];
    const float4* cache     = (const float4*)d_in[1];
    float4*       out       = (float4*)d_out;

    rope_gather_kernel<<<GRID, THREADS>>>(positions, cache, out);
}